// round 13
// baseline (speedup 1.0000x reference)
#include <cuda_runtime.h>
#include <cuda_fp16.h>
#include <cstdint>

// 3x3 s1 p1 conv, NCHW fp32 via mma.sync.m16n8k16 FP16 (f32 accumulate).
// R12 persistent kernel (83.8 us: 444 CTAs = 148x3, ring-of-6, 46 KB smem,
// 4-row warp phases, launch_bounds(256,3)) + vectorized build:
//  - build_row = 2x LDG.128 + 1x STS.128 per thread per row (edges by 32 thr),
//    +3 word shift for 16B-aligned STS.128 (R11-proven, conflict-free);
//    kills the div-by-66 scalar loop (~25% of issue slots).
//  - bias hoisted to per-warp registers (loaded once, not per phase).
// Warp = 1 m-tile (16 px) x 2 n-tiles (16 oc) x 4 rows per phase (C=32 regs).
// A: half2-packed [ic/2][px], stride 72 (conflict-free LDS.32 gathers).
// Direct sector-perfect STG.32 epilogue.

#define HW     256
#define ICN    32
#define OCN    32
#define SW     64            // tile strip width
#define YCH    8             // output rows per tile
#define NTILES 2048          // (256/SW) * (256/YCH) * 16 images
#define NCTA   444           // 148 SMs * 3 resident CTAs
#define STRIDE 72            // u32 per kp row (==8 mod 32 -> conflict-free)
#define KPN    16            // ic/2 packed rows
#define SLOT_U (KPN * STRIDE)              // 1152 u32 = 4608 B
#define B_BYTES (9 * 2 * 4 * 32 * 8)       // 18432
#define SM_A    B_BYTES
#define NSLOT   6
#define SMEM_TOTAL (B_BYTES + NSLOT * SLOT_U * 4)   // 46080 B

__device__ __forceinline__ uint32_t pack_h2(float a, float b) {
    uint32_t r;
    asm("cvt.rn.f16x2.f32 %0, %2, %1;" : "=r"(r) : "f"(a), "f"(b));
    return r;   // lo half = a, hi half = b
}

__device__ __forceinline__ void mma16(float c[4], uint32_t a0, uint32_t a1,
                                      uint32_t a2, uint32_t a3, uint2 b) {
    asm volatile(
        "mma.sync.aligned.m16n8k16.row.col.f32.f16.f16.f32 "
        "{%0,%1,%2,%3},{%4,%5,%6,%7},{%8,%9},{%0,%1,%2,%3};"
        : "+f"(c[0]), "+f"(c[1]), "+f"(c[2]), "+f"(c[3])
        : "r"(a0), "r"(a1), "r"(a2), "r"(a3), "r"(b.x), "r"(b.y));
}

// Stage input row yin into ring slot (yin mod 6).
// Word layout: slot[kp*STRIDE + px + 3], px in 0..65 <-> gx = x0-1+px.
// Interior (256 thr): kp=tid>>4, px=1+4*(tid&15): 2x LDG.128 + 1x STS.128
// (conflict-free per 8-lane octet). Edges (tid<32): px=0 / px=65 scalar.
__device__ __forceinline__ void build_row(const float* __restrict__ xn, int yin,
                                          int x0, uint32_t* __restrict__ smA,
                                          int tid) {
    uint32_t* slot = smA + ((yin + 12) % NSLOT) * SLOT_U;
    const bool yok = ((unsigned)yin < HW);
    const int kp = tid >> 4, gi = tid & 15;
    const int px = 1 + 4 * gi;                 // gx = x0 + 4*gi (16B aligned)
    float4 v0 = make_float4(0.f, 0.f, 0.f, 0.f), v1 = v0;
    if (yok) {
        const float* p = xn + (((size_t)kp * 2) << 16) + ((size_t)yin << 8)
                            + (x0 - 1 + px);
        v0 = *(const float4*)p;
        v1 = *(const float4*)(p + (1 << 16));
    }
    uint4 w;
    w.x = pack_h2(v0.x, v1.x);
    w.y = pack_h2(v0.y, v1.y);
    w.z = pack_h2(v0.z, v1.z);
    w.w = pack_h2(v0.w, v1.w);
    *(uint4*)(slot + kp * STRIDE + px + 3) = w;

    if (tid < 32) {
        const int kpe = tid & 15;
        const int pxe = (tid >> 4) ? 65 : 0;
        const int gxe = x0 - 1 + pxe;
        float a = 0.f, b = 0.f;
        if (yok && (unsigned)gxe < HW) {
            const float* p = xn + (((size_t)kpe * 2) << 16)
                               + ((size_t)yin << 8) + gxe;
            a = p[0];
            b = p[1 << 16];
        }
        slot[kpe * STRIDE + pxe + 3] = pack_h2(a, b);
    }
}

__global__ __launch_bounds__(256, 3)
void conv3x3_f16_r13_kernel(const float* __restrict__ xg,
                            const float* __restrict__ wg,
                            const float* __restrict__ bg,
                            float* __restrict__ out)
{
    extern __shared__ char smem[];
    uint32_t* smA = (uint32_t*)(smem + SM_A);
    const int tid  = threadIdx.x;
    const int warp = tid >> 5;
    const int lane = tid & 31;
    const int mt   = warp >> 1;     // m-tile 0..3
    const int nth  = warp & 1;      // n-tile half

    // ---- Stage B (fragment order): 2304 uint2 frags, ONCE per persistent CTA
    #pragma unroll
    for (int it = 0; it < 9; it++) {
        int idx  = tid + it * 256;
        int l    = idx & 31;
        int nt   = (idx >> 5) & 3;
        int k0   = (idx >> 7) & 1;
        int tap  = idx >> 8;                    // dy*3+dx
        int oc   = nt * 8 + (l >> 2);
        int ic0  = k0 * 16 + (l & 3) * 2;
        const float* wp = wg + (size_t)oc * ICN * 9 + tap;
        uint2 w2;
        w2.x = pack_h2(wp[(size_t)ic0 * 9],       wp[(size_t)(ic0 + 1) * 9]);
        w2.y = pack_h2(wp[(size_t)(ic0 + 8) * 9], wp[(size_t)(ic0 + 9) * 9]);
        *(uint2*)(smem + ((((tap * 2 + k0) * 4 + nt) * 32 + l) << 3)) = w2;
    }

    const int t = lane & 3, g = lane >> 2;
    const uint2* bw = (const uint2*)smem + lane;
    const uint32_t lbase = t * STRIDE + mt * 16 + g + 3;   // +3 layout shift

    // Bias hoisted once per persistent CTA
    float bv[2][2];
    #pragma unroll
    for (int j = 0; j < 2; j++) {
        int oc0 = (nth * 2 + j) * 8 + 2 * t;
        bv[j][0] = bg[oc0];
        bv[j][1] = bg[oc0 + 1];
    }

    // ---- Persistent tile loop: static stride over 2048 tiles
    #pragma unroll 1
    for (int tile = blockIdx.x; tile < NTILES; tile += NCTA) {
        const int x0 = (tile & 3) * SW;
        const int y0 = ((tile >> 2) & 31) * YCH;
        const int n  = tile >> 7;
        const float* xn = xg + (((size_t)n * ICN) << 16);
        const int gx = x0 + mt * 16 + g;

        __syncthreads();                // prior tile's slot readers done
        build_row(xn, y0 - 1, x0, smA, tid);
        build_row(xn, y0,     x0, smA, tid);

        #pragma unroll 1
        for (int p = 0; p < YCH / 4; p++) {
            const int y = y0 + 4 * p;       // rows y .. y+3

            __syncthreads();                // prev phase's LDS reads done
            build_row(xn, y + 1, x0, smA, tid);
            build_row(xn, y + 2, x0, smA, tid);
            build_row(xn, y + 3, x0, smA, tid);
            build_row(xn, y + 4, x0, smA, tid);
            __syncthreads();                // slots y-1 .. y+4 ready

            float c[4][2][4];
            #pragma unroll
            for (int r = 0; r < 4; r++)
                #pragma unroll
                for (int j = 0; j < 2; j++)
                    #pragma unroll
                    for (int i = 0; i < 4; i++) c[r][j][i] = 0.f;

            uint32_t so[NSLOT];
            #pragma unroll
            for (int i = 0; i < NSLOT; i++)
                so[i] = ((y - 1 + i + 12) % NSLOT) * SLOT_U + lbase;

            #pragma unroll
            for (int k0 = 0; k0 < 2; k0++) {
                #pragma unroll
                for (int dx = 0; dx < 3; dx++) {
                    // cache 6 B frags (3 dy x 2 nt) in regs
                    uint2 b[3][2];
                    #pragma unroll
                    for (int dy = 0; dy < 3; dy++)
                        #pragma unroll
                        for (int j = 0; j < 2; j++)
                            b[dy][j] = bw[(size_t)((((dy * 3 + dx) * 2 + k0) * 4
                                                    + nth * 2 + j)) * 32];

                    const int ao = k0 * 8 * STRIDE + dx;

                    #pragma unroll
                    for (int i = 0; i < NSLOT; i++) {
                        const uint32_t* s = smA + so[i] + ao;
                        uint32_t a0 = s[0], a1 = s[8];
                        uint32_t a2 = s[4 * STRIDE], a3 = s[4 * STRIDE + 8];
                        #pragma unroll
                        for (int dy = 0; dy < 3; dy++) {
                            int rl = i - dy;
                            if (rl >= 0 && rl < 4) {
                                mma16(c[rl][0], a0, a1, a2, a3, b[dy][0]);
                                mma16(c[rl][1], a0, a1, a2, a3, b[dy][1]);
                            }
                        }
                    }
                }
            }

            // ---- Epilogue: direct stores (sector-perfect STG.32)
            #pragma unroll
            for (int j = 0; j < 2; j++) {
                int oc0 = (nth * 2 + j) * 8 + 2 * t;
                #pragma unroll
                for (int rl = 0; rl < 4; rl++) {
                    float* o = out + (((size_t)(n * OCN + oc0)) << 16)
                                   + ((size_t)(y + rl) << 8) + gx;
                    o[0]                     = c[rl][j][0] + bv[j][0];
                    o[(size_t)1 << 16]       = c[rl][j][1] + bv[j][1];
                    o[8]                     = c[rl][j][2] + bv[j][0];
                    o[((size_t)1 << 16) + 8] = c[rl][j][3] + bv[j][1];
                }
            }
        }
    }
}

extern "C" void kernel_launch(void* const* d_in, const int* in_sizes, int n_in,
                              void* d_out, int out_size) {
    const float* x = (const float*)d_in[0];
    const float* w = (const float*)d_in[1];
    const float* b = (const float*)d_in[2];
    float* out = (float*)d_out;

    cudaFuncSetAttribute(conv3x3_f16_r13_kernel,
                         cudaFuncAttributeMaxDynamicSharedMemorySize, SMEM_TOTAL);

    conv3x3_f16_r13_kernel<<<NCTA, 256, SMEM_TOTAL>>>(x, w, b, out);
}

// round 14
// speedup vs baseline: 1.0688x; 1.0688x over previous
#include <cuda_runtime.h>
#include <cuda_fp16.h>
#include <cstdint>

// 3x3 s1 p1 conv, NCHW fp32 via mma.sync.m16n8k16 FP16 (f32 accumulate).
// R12 core (83.8 us: persistent 444 CTAs, 4-row warp phases, scalar build,
// launch_bounds(256,3)) with a build-AHEAD pipeline on a static ring-of-10:
//  tile = 10 input rows -> slot(j) = j+1 (static, no modulo).
//  - slots 0-3 built right after prev tile's phase-1 compute (NO sync first:
//    overlaps straggler warps' MMAs; slots disjoint from phase-1 reads 4-9)
//  - sync; slots 4,5 built (only 2 exposed rows); sync
//  - phase0 computes rows y0..y0+3 (slots 0-5), THEN builds slots 6-9
//    (staggered warp exit from MMAs overlaps the LDGs); sync
//  - phase1 computes rows y0+4..y0+7 (slots 4-9); loop.
//  3 syncs/tile (was 5), 8 of 10 row-builds overlapped (was 0).
// Warp = 1 m-tile (16 px) x 2 n-tiles (16 oc) x 4 rows per phase (C=32 regs).
// A: half2-packed [ic/2][px], stride 72 (conflict-free LDS.32 gathers).
// Smem 64.5 KB -> 3 CTAs/SM (193.5 KB, L1 carveout ~34 KB - the tested risk).

#define HW     256
#define ICN    32
#define OCN    32
#define SW     64            // tile strip width
#define YCH    8             // output rows per tile
#define NTILES 2048          // (256/SW) * (256/YCH) * 16 images
#define NCTA   444           // 148 SMs * 3 resident CTAs
#define XW     66            // strip + halo
#define STRIDE 72            // u32 per kp row (==8 mod 32 -> conflict-free)
#define KPN    16            // ic/2 packed rows
#define SLOT_U (KPN * STRIDE)              // 1152 u32 = 4608 B
#define B_BYTES (9 * 2 * 4 * 32 * 8)       // 18432
#define SM_A    B_BYTES
#define NSLOT   10
#define SMEM_TOTAL (B_BYTES + NSLOT * SLOT_U * 4)   // 64512 B

__device__ __forceinline__ uint32_t pack_h2(float a, float b) {
    uint32_t r;
    asm("cvt.rn.f16x2.f32 %0, %2, %1;" : "=r"(r) : "f"(a), "f"(b));
    return r;   // lo half = a, hi half = b
}

__device__ __forceinline__ void mma16(float c[4], uint32_t a0, uint32_t a1,
                                      uint32_t a2, uint32_t a3, uint2 b) {
    asm volatile(
        "mma.sync.aligned.m16n8k16.row.col.f32.f16.f16.f32 "
        "{%0,%1,%2,%3},{%4,%5,%6,%7},{%8,%9},{%0,%1,%2,%3};"
        : "+f"(c[0]), "+f"(c[1]), "+f"(c[2]), "+f"(c[3])
        : "r"(a0), "r"(a1), "r"(a2), "r"(a3), "r"(b.x), "r"(b.y));
}

// Stage input row yin into the given slot: half2-packed [ic/2][px], scalar
// (high per-thread MLP - R13 proved wide loads hurt here).
__device__ __forceinline__ void build_row(const float* __restrict__ xn, int yin,
                                          int x0, uint32_t* __restrict__ slot,
                                          int tid) {
    bool yok = ((unsigned)yin < HW);
    const float* xr = xn + ((size_t)yin << 8);
    #pragma unroll
    for (int e = tid; e < KPN * XW; e += 256) {
        int kp = e / XW;
        int px = e - kp * XW;
        int gx = x0 - 1 + px;
        float v0 = 0.f, v1 = 0.f;
        if (yok && (unsigned)gx < HW) {
            const float* p = xr + (((size_t)kp * 2) << 16) + gx;
            v0 = p[0];
            v1 = p[1 << 16];
        }
        slot[kp * STRIDE + px] = pack_h2(v0, v1);
    }
}

__global__ __launch_bounds__(256, 3)
void conv3x3_f16_r14_kernel(const float* __restrict__ xg,
                            const float* __restrict__ wg,
                            const float* __restrict__ bg,
                            float* __restrict__ out)
{
    extern __shared__ char smem[];
    uint32_t* smA = (uint32_t*)(smem + SM_A);
    const int tid  = threadIdx.x;
    const int warp = tid >> 5;
    const int lane = tid & 31;
    const int mt   = warp >> 1;     // m-tile 0..3
    const int nth  = warp & 1;      // n-tile half

    // ---- Stage B (fragment order): 2304 uint2 frags, ONCE per persistent CTA
    #pragma unroll
    for (int it = 0; it < 9; it++) {
        int idx  = tid + it * 256;
        int l    = idx & 31;
        int nt   = (idx >> 5) & 3;
        int k0   = (idx >> 7) & 1;
        int tap  = idx >> 8;                    // dy*3+dx
        int oc   = nt * 8 + (l >> 2);
        int ic0  = k0 * 16 + (l & 3) * 2;
        const float* wp = wg + (size_t)oc * ICN * 9 + tap;
        uint2 w2;
        w2.x = pack_h2(wp[(size_t)ic0 * 9],       wp[(size_t)(ic0 + 1) * 9]);
        w2.y = pack_h2(wp[(size_t)(ic0 + 8) * 9], wp[(size_t)(ic0 + 9) * 9]);
        *(uint2*)(smem + ((((tap * 2 + k0) * 4 + nt) * 32 + l) << 3)) = w2;
    }

    const int t = lane & 3, g = lane >> 2;
    const uint2* bw = (const uint2*)smem + lane;
    const uint32_t lbase = t * STRIDE + mt * 16 + g;

    // Bias hoisted once per persistent CTA
    float bv[2][2];
    #pragma unroll
    for (int j = 0; j < 2; j++) {
        int oc0 = (nth * 2 + j) * 8 + 2 * t;
        bv[j][0] = bg[oc0];
        bv[j][1] = bg[oc0 + 1];
    }

    // ---- Persistent tile loop; slot(j) = j+1 for input row y0+j, j=-1..8
    #pragma unroll 1
    for (int tile = blockIdx.x; tile < NTILES; tile += NCTA) {
        const int x0 = (tile & 3) * SW;
        const int y0 = ((tile >> 2) & 31) * YCH;
        const int n  = tile >> 7;
        const float* xn = xg + (((size_t)n * ICN) << 16);
        const int gx = x0 + mt * 16 + g;

        // step 1: slots 0-3 (rows y0-1..y0+2); prev phase-1 reads slots 4-9,
        // disjoint -> NO sync: overlaps straggler warps' compute.
        build_row(xn, y0 - 1, x0, smA + 0 * SLOT_U, tid);
        build_row(xn, y0,     x0, smA + 1 * SLOT_U, tid);
        build_row(xn, y0 + 1, x0, smA + 2 * SLOT_U, tid);
        build_row(xn, y0 + 2, x0, smA + 3 * SLOT_U, tid);
        __syncthreads();            // prev tile's phase-1 readers done

        // step 2: slots 4,5 (rows y0+3, y0+4) - the only exposed builds
        build_row(xn, y0 + 3, x0, smA + 4 * SLOT_U, tid);
        build_row(xn, y0 + 4, x0, smA + 5 * SLOT_U, tid);
        __syncthreads();            // slots 0-5 ready

        #pragma unroll 1
        for (int p = 0; p < 2; p++) {
            const int y = y0 + 4 * p;       // rows y .. y+3, read slots 4p..4p+5

            float c[4][2][4];
            #pragma unroll
            for (int r = 0; r < 4; r++)
                #pragma unroll
                for (int j = 0; j < 2; j++)
                    #pragma unroll
                    for (int i = 0; i < 4; i++) c[r][j][i] = 0.f;

            const uint32_t sbase = (uint32_t)(4 * p) * SLOT_U + lbase;

            #pragma unroll
            for (int k0 = 0; k0 < 2; k0++) {
                #pragma unroll
                for (int dx = 0; dx < 3; dx++) {
                    // cache 6 B frags (3 dy x 2 nt) in regs
                    uint2 b[3][2];
                    #pragma unroll
                    for (int dy = 0; dy < 3; dy++)
                        #pragma unroll
                        for (int j = 0; j < 2; j++)
                            b[dy][j] = bw[(size_t)((((dy * 3 + dx) * 2 + k0) * 4
                                                    + nth * 2 + j)) * 32];

                    const uint32_t* s = smA + sbase + k0 * 8 * STRIDE + dx;

                    #pragma unroll
                    for (int i = 0; i < 6; i++) {
                        uint32_t a0 = s[0], a1 = s[8];
                        uint32_t a2 = s[4 * STRIDE], a3 = s[4 * STRIDE + 8];
                        #pragma unroll
                        for (int dy = 0; dy < 3; dy++) {
                            int rl = i - dy;
                            if (rl >= 0 && rl < 4) {
                                mma16(c[rl][0], a0, a1, a2, a3, b[dy][0]);
                                mma16(c[rl][1], a0, a1, a2, a3, b[dy][1]);
                            }
                        }
                        s += SLOT_U;
                    }
                }
            }

            // phase-0 trailing builds: slots 6-9 (rows y0+5..y0+8).
            // Warps exit the MMA block staggered -> LDGs overlap other warps'
            // compute. Slots disjoint from phase-0 reads (0-5): no sync needed.
            if (p == 0) {
                build_row(xn, y0 + 5, x0, smA + 6 * SLOT_U, tid);
                build_row(xn, y0 + 6, x0, smA + 7 * SLOT_U, tid);
                build_row(xn, y0 + 7, x0, smA + 8 * SLOT_U, tid);
                build_row(xn, y0 + 8, x0, smA + 9 * SLOT_U, tid);
            }

            // ---- Epilogue: direct stores (sector-perfect STG.32)
            #pragma unroll
            for (int j = 0; j < 2; j++) {
                int oc0 = (nth * 2 + j) * 8 + 2 * t;
                #pragma unroll
                for (int rl = 0; rl < 4; rl++) {
                    float* o = out + (((size_t)(n * OCN + oc0)) << 16)
                                   + ((size_t)(y + rl) << 8) + gx;
                    o[0]                     = c[rl][j][0] + bv[j][0];
                    o[(size_t)1 << 16]       = c[rl][j][1] + bv[j][1];
                    o[8]                     = c[rl][j][2] + bv[j][0];
                    o[((size_t)1 << 16) + 8] = c[rl][j][3] + bv[j][1];
                }
            }

            if (p == 0) __syncthreads();    // slots 6-9 ready; 0-3 readers done
        }
        // loop: next tile's step-1 builds (slots 0-3) overlap this phase-1
    }
}

extern "C" void kernel_launch(void* const* d_in, const int* in_sizes, int n_in,
                              void* d_out, int out_size) {
    const float* x = (const float*)d_in[0];
    const float* w = (const float*)d_in[1];
    const float* b = (const float*)d_in[2];
    float* out = (float*)d_out;

    cudaFuncSetAttribute(conv3x3_f16_r14_kernel,
                         cudaFuncAttributeMaxDynamicSharedMemorySize, SMEM_TOTAL);

    conv3x3_f16_r14_kernel<<<NCTA, 256, SMEM_TOTAL>>>(x, w, b, out);
}